// round 2
// baseline (speedup 1.0000x reference)
#include <cuda_runtime.h>

#define EPSF 1e-6f
constexpr int B_ = 8;      // batch
constexpr int C_ = 512;    // channels (= D)
constexpr int N_ = 4096;   // spatial H*W
constexpr int R_ = 64;     // bases rank

// ---------------- scratch (device globals; no allocation) ----------------
__device__ float g_h1  [(size_t)B_*C_*N_];   // relu(lower conv)   64 MB
__device__ float g_ham [(size_t)B_*C_*N_];   // bases @ coef^T     64 MB
__device__ float g_h2  [(size_t)B_*C_*N_];   // relu(cheese)       64 MB
__device__ float g_bases[(size_t)B_*C_*R_];
__device__ float g_coef [(size_t)B_*N_*R_];
__device__ float g_xtb  [(size_t)B_*N_*R_];
__device__ float g_btb  [(size_t)B_*R_*R_];
__device__ float g_ctc_part[(size_t)16*B_*R_*R_];
__device__ float g_xc_part [(size_t)8*B_*C_*R_];

// ---------------- packed f32x2 helpers ----------------
__device__ __forceinline__ double ffma2(double a, double b, double c) {
    double d;
    asm("fma.rn.f32x2 %0, %1, %2, %3;" : "=d"(d) : "d"(a), "d"(b), "d"(c));
    return d;
}
__device__ __forceinline__ float2 unpack2(double d) {
    float2 f; asm("mov.b64 {%0, %1}, %2;" : "=f"(f.x), "=f"(f.y) : "d"(d)); return f;
}
__device__ __forceinline__ double pack2(float x) {
    double d; asm("mov.b64 %0, {%1, %1};" : "=d"(d) : "f"(x)); return d;
}

// ---------------- l2 normalize bases0 over D ----------------
__global__ void k_l2norm(const float* __restrict__ b0)
{
    int b = blockIdx.x >> 6, r = blockIdx.x & 63;
    const float* src = b0 + (size_t)b*C_*R_ + r;
    float ss = 0.f;
    for (int d = threadIdx.x; d < C_; d += 128) { float v = src[(size_t)d*R_]; ss += v*v; }
    __shared__ float red[128];
    red[threadIdx.x] = ss; __syncthreads();
    for (int s = 64; s > 0; s >>= 1) {
        if (threadIdx.x < s) red[threadIdx.x] += red[threadIdx.x + s];
        __syncthreads();
    }
    float inv = 1.f / fmaxf(sqrtf(red[0]), 1e-12f);
    float* dst = g_bases + (size_t)b*C_*R_ + r;
    for (int d = threadIdx.x; d < C_; d += 128) dst[(size_t)d*R_] = src[(size_t)d*R_] * inv;
}

// ---------------- big SGEMM: Y[b] = epilogue(W @ X[b]) ----------------
// W: [512,512] row-major, X: [B,512,4096], tiles 128x128x8, 256 thr, 8x8 micro
// FFMA2: A duplicated in smem, outer-product pairs along N. Prefetched.
template<int SEL>
__global__ __launch_bounds__(256) void k_gemm512(
    const float* __restrict__ W, const float* __restrict__ xin,
    const float* __restrict__ bias, const float* __restrict__ shortcut,
    const float* __restrict__ p_ham, const float* __restrict__ p_sc,
    float* __restrict__ dout)
{
    const float* X = (SEL == 0) ? xin : (SEL == 1) ? g_ham : g_h2;
    float*       Y = (SEL == 0) ? g_h1 : (SEL == 1) ? g_h2 : dout;

    int b  = blockIdx.z;
    int m0 = blockIdx.y * 128;
    int n0 = blockIdx.x * 128;
    const float* Xb = X + (size_t)b*C_*N_;

    __shared__ float As2[8][256];   // duplicated A: As2[k][2*row], As2[k][2*row+1]
    __shared__ float Bs [8][132];

    int t  = threadIdx.x;
    int tx = t & 15, ty = t >> 4;
    double acc[8][4];
#pragma unroll
    for (int i = 0; i < 8; i++)
#pragma unroll
        for (int j = 0; j < 4; j++) acc[i][j] = 0.0;

    int arow = t >> 1, acol = (t & 1) * 4;
    int brow = t >> 5, bcol = (t & 31) * 4;
    const float* Aptr = W  + (size_t)(m0 + arow)*C_ + acol;
    const float* Bptr = Xb + (size_t)brow*N_ + n0 + bcol;

    float4 av = *(const float4*)Aptr;
    float4 bv = *(const float4*)Bptr;

    for (int k0 = 0; k0 < C_; k0 += 8) {
        __syncthreads();
        {
            float2 d0 = {av.x, av.x}, d1 = {av.y, av.y};
            float2 d2 = {av.z, av.z}, d3 = {av.w, av.w};
            *(float2*)&As2[acol+0][2*arow] = d0;
            *(float2*)&As2[acol+1][2*arow] = d1;
            *(float2*)&As2[acol+2][2*arow] = d2;
            *(float2*)&As2[acol+3][2*arow] = d3;
            *(float4*)&Bs[brow][bcol] = bv;
        }
        __syncthreads();
        if (k0 + 8 < C_) {
            av = *(const float4*)(Aptr + k0 + 8);
            bv = *(const float4*)(Bptr + (size_t)(k0 + 8)*N_);
        }
#pragma unroll
        for (int k = 0; k < 8; k++) {
            const double2* ap  = (const double2*)&As2[k][ty*16];
            const double2* bp2 = (const double2*)&Bs[k][tx*8];
            double2 a01 = ap[0], a23 = ap[1], a45 = ap[2], a67 = ap[3];
            double2 b01 = bp2[0], b23 = bp2[1];
            double ar[8] = {a01.x, a01.y, a23.x, a23.y, a45.x, a45.y, a67.x, a67.y};
            double br[4] = {b01.x, b01.y, b23.x, b23.y};
#pragma unroll
            for (int i = 0; i < 8; i++)
#pragma unroll
                for (int j = 0; j < 4; j++) acc[i][j] = ffma2(ar[i], br[j], acc[i][j]);
        }
    }

    float ch = 1.f, cs = 1.f;
    if (SEL == 2) { ch = p_ham[0]; cs = p_sc[0]; }
#pragma unroll
    for (int i = 0; i < 8; i++) {
        int m = m0 + ty*8 + i;
        float* yp = Y + (size_t)b*C_*N_ + (size_t)m*N_ + n0 + tx*8;
        float2 p0 = unpack2(acc[i][0]), p1 = unpack2(acc[i][1]);
        float2 p2 = unpack2(acc[i][2]), p3 = unpack2(acc[i][3]);
        float r0 = p0.x, r1 = p0.y, r2 = p1.x, r3 = p1.y;
        float r4 = p2.x, r5 = p2.y, r6 = p3.x, r7 = p3.y;
        if (SEL != 2) {
            float bvv = bias[m];
            float4 o0, o1;
            o0.x = fmaxf(r0+bvv, 0.f); o0.y = fmaxf(r1+bvv, 0.f);
            o0.z = fmaxf(r2+bvv, 0.f); o0.w = fmaxf(r3+bvv, 0.f);
            o1.x = fmaxf(r4+bvv, 0.f); o1.y = fmaxf(r5+bvv, 0.f);
            o1.z = fmaxf(r6+bvv, 0.f); o1.w = fmaxf(r7+bvv, 0.f);
            *(float4*)yp = o0; *(float4*)(yp+4) = o1;
        } else {
            const float* sp = shortcut + (size_t)b*C_*N_ + (size_t)m*N_ + n0 + tx*8;
            float4 s0 = *(const float4*)sp, s1 = *(const float4*)(sp+4);
            float4 o0, o1;
            o0.x = fmaxf(ch*r0 + cs*s0.x, 0.f);
            o0.y = fmaxf(ch*r1 + cs*s0.y, 0.f);
            o0.z = fmaxf(ch*r2 + cs*s0.z, 0.f);
            o0.w = fmaxf(ch*r3 + cs*s0.w, 0.f);
            o1.x = fmaxf(ch*r4 + cs*s1.x, 0.f);
            o1.y = fmaxf(ch*r5 + cs*s1.y, 0.f);
            o1.z = fmaxf(ch*r6 + cs*s1.z, 0.f);
            o1.w = fmaxf(ch*r7 + cs*s1.w, 0.f);
            *(float4*)yp = o0; *(float4*)(yp+4) = o1;
        }
    }
}

// ---------------- xtb[b,n,r] = sum_d h1[b,d,n] * bases[b,d,r] ----------------
// tiles: 128 n x 64 r, K=16; FFMA2 pairs along n, bases duplicated. Prefetched.
__global__ __launch_bounds__(256) void k_xtb()
{
    int n0 = blockIdx.x * 128, b = blockIdx.y;
    const float* xb = g_h1    + (size_t)b*C_*N_;
    const float* bp = g_bases + (size_t)b*C_*R_;
    __shared__ float xs [16][128];
    __shared__ float bs2[16][128];   // duplicated bases
    int t = threadIdx.x;
    int tn = t & 15, tr = t >> 4;
    int lrow = t >> 4, xcol = (t & 15) * 8, bcol = (t & 15) * 4;
    double acc[4][4];
#pragma unroll
    for (int i = 0; i < 4; i++)
#pragma unroll
        for (int j = 0; j < 4; j++) acc[i][j] = 0.0;

    const float* xptr = xb + (size_t)lrow*N_ + n0 + xcol;
    const float* bptr = bp + (size_t)lrow*R_ + bcol;
    float4 x0 = *(const float4*)xptr;
    float4 x1 = *(const float4*)(xptr + 4);
    float4 b0 = *(const float4*)bptr;

    for (int d0 = 0; d0 < C_; d0 += 16) {
        __syncthreads();
        *(float4*)&xs[lrow][xcol]   = x0;
        *(float4*)&xs[lrow][xcol+4] = x1;
        {
            float2 e0 = {b0.x, b0.x}, e1 = {b0.y, b0.y};
            float2 e2 = {b0.z, b0.z}, e3 = {b0.w, b0.w};
            *(float2*)&bs2[lrow][2*bcol+0] = e0;
            *(float2*)&bs2[lrow][2*bcol+2] = e1;
            *(float2*)&bs2[lrow][2*bcol+4] = e2;
            *(float2*)&bs2[lrow][2*bcol+6] = e3;
        }
        __syncthreads();
        if (d0 + 16 < C_) {
            x0 = *(const float4*)(xptr + (size_t)(d0+16)*N_);
            x1 = *(const float4*)(xptr + (size_t)(d0+16)*N_ + 4);
            b0 = *(const float4*)(bptr + (size_t)(d0+16)*R_);
        }
#pragma unroll
        for (int k = 0; k < 16; k++) {
            const double2* ap  = (const double2*)&xs[k][tn*8];
            const double2* bdp = (const double2*)&bs2[k][tr*8];
            double2 a01 = ap[0], a23 = ap[1];
            double2 b01 = bdp[0], b23 = bdp[1];
            double ar[4] = {a01.x, a01.y, a23.x, a23.y};
            double br[4] = {b01.x, b01.y, b23.x, b23.y};
#pragma unroll
            for (int i = 0; i < 4; i++)
#pragma unroll
                for (int j = 0; j < 4; j++) acc[i][j] = ffma2(ar[i], br[j], acc[i][j]);
        }
    }
    float* op = g_xtb + ((size_t)b*N_ + n0 + tn*8)*R_ + tr*4;
#pragma unroll
    for (int i = 0; i < 4; i++) {
        float2 p0 = unpack2(acc[i][0]), p1 = unpack2(acc[i][1]);
        float2 p2 = unpack2(acc[i][2]), p3 = unpack2(acc[i][3]);
        float4 olo = {p0.x, p1.x, p2.x, p3.x};
        float4 ohi = {p0.y, p1.y, p2.y, p3.y};
        *(float4*)(op + (size_t)(2*i  )*R_) = olo;
        *(float4*)(op + (size_t)(2*i+1)*R_) = ohi;
    }
}

// ---------------- coef init: softmax over r of xtb ----------------
__global__ void k_softmax()
{
    int row  = blockIdx.x * 8 + (threadIdx.x >> 5);
    int lane = threadIdx.x & 31;
    const float* xp = g_xtb + (size_t)row*R_;
    float v0 = xp[lane], v1 = xp[lane+32];
    float m = fmaxf(v0, v1);
#pragma unroll
    for (int o = 16; o; o >>= 1) m = fmaxf(m, __shfl_xor_sync(0xffffffffu, m, o));
    float e0 = __expf(v0 - m), e1 = __expf(v1 - m);
    float s = e0 + e1;
#pragma unroll
    for (int o = 16; o; o >>= 1) s += __shfl_xor_sync(0xffffffffu, s, o);
    float inv = 1.f / s;
    float* op = g_coef + (size_t)row*R_;
    op[lane] = e0*inv; op[lane+32] = e1*inv;
}

// ---------------- btb[b,r,s] = sum_d bases[b,d,r]*bases[b,d,s] ----------------
__global__ __launch_bounds__(256) void k_btb()
{
    int b = blockIdx.x, g = blockIdx.y;
    const float* bp = g_bases + (size_t)b*C_*R_;
    __shared__ float sh[32][64];
    int t = threadIdx.x;
    int r = g*4 + (t >> 6), s = t & 63;
    float acc = 0.f;
    for (int d0 = 0; d0 < C_; d0 += 32) {
        __syncthreads();
        for (int i = t; i < 2048; i += 256) sh[i>>6][i&63] = bp[(size_t)d0*R_ + i];
        __syncthreads();
#pragma unroll
        for (int d = 0; d < 32; d++) acc += sh[d][r]*sh[d][s];
    }
    g_btb[((size_t)b*R_ + r)*R_ + s] = acc;
}

// ---------------- coef *= xtb / (coef @ btb + eps), in-place ----------------
__global__ __launch_bounds__(256) void k_coef_update()
{
    int b = blockIdx.y, n0 = blockIdx.x * 32;
    __shared__ float bt[64][64];
    __shared__ float cr[32][64];
    int t = threadIdx.x;
    const float* bp = g_btb + (size_t)b*R_*R_;
    for (int i = t; i < 4096; i += 256) bt[i>>6][i&63] = bp[i];
    const float* cp = g_coef + ((size_t)b*N_ + n0)*R_;
    for (int i = t; i < 2048; i += 256) cr[i>>6][i&63] = cp[i];
    __syncthreads();
    int nl = t >> 3, r0 = (t & 7) * 8;
    float acc[8] = {0,0,0,0,0,0,0,0};
#pragma unroll 8
    for (int s = 0; s < 64; s++) {
        float c = cr[nl][s];
        float4 b0 = *(float4*)&bt[s][r0], b1 = *(float4*)&bt[s][r0+4];
        acc[0] += c*b0.x; acc[1] += c*b0.y; acc[2] += c*b0.z; acc[3] += c*b0.w;
        acc[4] += c*b1.x; acc[5] += c*b1.y; acc[6] += c*b1.z; acc[7] += c*b1.w;
    }
    const float* xp = g_xtb + ((size_t)b*N_ + n0 + nl)*R_ + r0;
    float* op = g_coef + ((size_t)b*N_ + n0 + nl)*R_ + r0;
#pragma unroll
    for (int j = 0; j < 8; j++) op[j] = cr[nl][r0+j] * xp[j] / (acc[j] + EPSF);
}

// ---------------- xc partials: split-K over n (8 splits x 512) ----------------
// FFMA2 pairs along d, coef duplicated. Prefetched.
__global__ __launch_bounds__(256) void k_xc_part()
{
    int m0 = blockIdx.x * 128, b = blockIdx.y, sp = blockIdx.z;
    const float* xb = g_h1   + (size_t)b*C_*N_ + sp*512;
    const float* cp = g_coef + ((size_t)b*N_ + sp*512)*R_;
    __shared__ float xs [16][128];   // transposed: xs[n_k][d]
    __shared__ float cs2[16][128];   // duplicated coef
    int t = threadIdx.x;
    int td = t & 15, tr = t >> 4;
    int lrow = t >> 1, lnc = (t & 1) * 8;
    int crow = t >> 4, ccol = (t & 15) * 4;
    double acc[4][4];
#pragma unroll
    for (int i = 0; i < 4; i++)
#pragma unroll
        for (int j = 0; j < 4; j++) acc[i][j] = 0.0;

    const float* xptr = xb + (size_t)(m0 + lrow)*N_ + lnc;
    const float* cptr = cp + (size_t)crow*R_ + ccol;
    float4 x0 = *(const float4*)xptr;
    float4 x1 = *(const float4*)(xptr + 4);
    float4 c0 = *(const float4*)cptr;

    for (int n0 = 0; n0 < 512; n0 += 16) {
        __syncthreads();
        xs[lnc+0][lrow] = x0.x; xs[lnc+1][lrow] = x0.y;
        xs[lnc+2][lrow] = x0.z; xs[lnc+3][lrow] = x0.w;
        xs[lnc+4][lrow] = x1.x; xs[lnc+5][lrow] = x1.y;
        xs[lnc+6][lrow] = x1.z; xs[lnc+7][lrow] = x1.w;
        {
            float2 e0 = {c0.x, c0.x}, e1 = {c0.y, c0.y};
            float2 e2 = {c0.z, c0.z}, e3 = {c0.w, c0.w};
            *(float2*)&cs2[crow][2*ccol+0] = e0;
            *(float2*)&cs2[crow][2*ccol+2] = e1;
            *(float2*)&cs2[crow][2*ccol+4] = e2;
            *(float2*)&cs2[crow][2*ccol+6] = e3;
        }
        __syncthreads();
        if (n0 + 16 < 512) {
            x0 = *(const float4*)(xptr + n0 + 16);
            x1 = *(const float4*)(xptr + n0 + 16 + 4);
            c0 = *(const float4*)(cptr + (size_t)(n0+16)*R_);
        }
#pragma unroll
        for (int k = 0; k < 16; k++) {
            const double2* ap  = (const double2*)&xs[k][td*8];
            const double2* cdp = (const double2*)&cs2[k][tr*8];
            double2 a01 = ap[0], a23 = ap[1];
            double2 c01 = cdp[0], c23 = cdp[1];
            double ar[4] = {a01.x, a01.y, a23.x, a23.y};
            double cr2[4] = {c01.x, c01.y, c23.x, c23.y};
#pragma unroll
            for (int i = 0; i < 4; i++)
#pragma unroll
                for (int j = 0; j < 4; j++) acc[i][j] = ffma2(ar[i], cr2[j], acc[i][j]);
        }
    }
    float* op = g_xc_part + ((size_t)(sp*8 + b)*C_ + m0 + td*8)*R_ + tr*4;
#pragma unroll
    for (int i = 0; i < 4; i++) {
        float2 p0 = unpack2(acc[i][0]), p1 = unpack2(acc[i][1]);
        float2 p2 = unpack2(acc[i][2]), p3 = unpack2(acc[i][3]);
        float4 olo = {p0.x, p1.x, p2.x, p3.x};
        float4 ohi = {p0.y, p1.y, p2.y, p3.y};
        *(float4*)(op + (size_t)(2*i  )*R_) = olo;
        *(float4*)(op + (size_t)(2*i+1)*R_) = ohi;
    }
}

// ---------------- ctc partials: split over n (16 splits x 256) ----------------
__global__ __launch_bounds__(256) void k_ctc_part()
{
    int b = blockIdx.x, sp = blockIdx.y;
    const float* cp = g_coef + ((size_t)b*N_ + sp*256)*R_;
    __shared__ float sh[32][64];
    int t = threadIdx.x;
    int rg = t >> 4, cg = t & 15;
    float acc[4][4];
#pragma unroll
    for (int i = 0; i < 4; i++)
#pragma unroll
        for (int j = 0; j < 4; j++) acc[i][j] = 0.f;

    for (int n0 = 0; n0 < 256; n0 += 32) {
        __syncthreads();
        for (int i = t; i < 2048; i += 256) sh[i>>6][i&63] = cp[(size_t)n0*R_ + i];
        __syncthreads();
#pragma unroll 4
        for (int n = 0; n < 32; n++) {
            float4 a = *(float4*)&sh[n][rg*4];
            float4 c = *(float4*)&sh[n][cg*4];
            float av[4] = {a.x,a.y,a.z,a.w}, cv[4] = {c.x,c.y,c.z,c.w};
#pragma unroll
            for (int i = 0; i < 4; i++)
#pragma unroll
                for (int j = 0; j < 4; j++) acc[i][j] += av[i]*cv[j];
        }
    }
    float* op = g_ctc_part + ((size_t)(sp*8 + b)*R_ + rg*4)*R_ + cg*4;
#pragma unroll
    for (int i = 0; i < 4; i++) {
        float4 o = {acc[i][0], acc[i][1], acc[i][2], acc[i][3]};
        *(float4*)(op + (size_t)i*R_) = o;
    }
}

// ---------------- bases *= xc / (bases @ ctc + eps), in-place ----------------
__global__ __launch_bounds__(256) void k_bases_update()
{
    int b = blockIdx.x, d0 = blockIdx.y * 64;
    __shared__ float ct[64][64];
    __shared__ float br[64][64];
    int t = threadIdx.x;
    for (int i = t; i < 4096; i += 256) {
        float s = 0.f;
#pragma unroll
        for (int p = 0; p < 16; p++) s += g_ctc_part[(size_t)(p*8 + b)*4096 + i];
        ct[i>>6][i&63] = s;
    }
    const float* bp = g_bases + ((size_t)b*C_ + d0)*R_;
    for (int i = t; i < 4096; i += 256) br[i>>6][i&63] = bp[i];
    __syncthreads();
    int dl = t >> 2, r0 = (t & 3) * 16;
    float acc[16];
#pragma unroll
    for (int j = 0; j < 16; j++) acc[j] = 0.f;
#pragma unroll 4
    for (int s = 0; s < 64; s++) {
        float bv = br[dl][s];
#pragma unroll
        for (int j4 = 0; j4 < 16; j4 += 4) {
            float4 v = *(float4*)&ct[s][r0 + j4];
            acc[j4+0] += bv*v.x; acc[j4+1] += bv*v.y;
            acc[j4+2] += bv*v.z; acc[j4+3] += bv*v.w;
        }
    }
    float xcs[16];
#pragma unroll
    for (int j = 0; j < 16; j++) xcs[j] = 0.f;
#pragma unroll
    for (int p = 0; p < 8; p++) {
        const float* xp = g_xc_part + ((size_t)(p*8 + b)*C_ + d0 + dl)*R_ + r0;
#pragma unroll
        for (int j4 = 0; j4 < 16; j4 += 4) {
            float4 v = *(const float4*)(xp + j4);
            xcs[j4+0] += v.x; xcs[j4+1] += v.y; xcs[j4+2] += v.z; xcs[j4+3] += v.w;
        }
    }
    float* op = g_bases + ((size_t)b*C_ + d0 + dl)*R_ + r0;
#pragma unroll
    for (int j = 0; j < 16; j++) op[j] = br[dl][r0+j] * xcs[j] / (acc[j] + EPSF);
}

// ---------------- ham[b,d,n] = sum_r bases[b,d,r]*coef[b,n,r] ----------------
// tiles 64d x 64n, K=64 resident; FFMA2 pairs along n via transposed coef tile
__global__ __launch_bounds__(256) void k_ham()
{
    int b = blockIdx.z, d0 = blockIdx.y * 64, n0 = blockIdx.x * 64;
    __shared__ float bs  [64][65];
    __shared__ float cs_t[64][66];   // transposed: cs_t[r][n]; 66 keeps rows 8B-aligned
    int t = threadIdx.x;
    const float* bp = g_bases + ((size_t)b*C_ + d0)*R_;
    const float* cp = g_coef  + ((size_t)b*N_ + n0)*R_;
    for (int i = t; i < 4096; i += 256) {
        bs[i>>6][i&63] = bp[i];
        cs_t[i&63][i>>6] = cp[i];
    }
    __syncthreads();
    int td = t >> 4, tn = t & 15;
    double acc[4][2];
#pragma unroll
    for (int i = 0; i < 4; i++) { acc[i][0] = 0.0; acc[i][1] = 0.0; }
#pragma unroll 4
    for (int r = 0; r < 64; r++) {
        const double* cvp = (const double*)&cs_t[r][tn*4];
        double cv0 = cvp[0], cv1 = cvp[1];
#pragma unroll
        for (int i = 0; i < 4; i++) {
            double a = pack2(bs[td*4+i][r]);
            acc[i][0] = ffma2(a, cv0, acc[i][0]);
            acc[i][1] = ffma2(a, cv1, acc[i][1]);
        }
    }
#pragma unroll
    for (int i = 0; i < 4; i++) {
        float* op = g_ham + (size_t)b*C_*N_ + (size_t)(d0 + td*4 + i)*N_ + n0 + tn*4;
        float2 p0 = unpack2(acc[i][0]), p1 = unpack2(acc[i][1]);
        float4 o = {p0.x, p0.y, p1.x, p1.y};
        *(float4*)op = o;
    }
}

// ---------------- host driver ----------------
extern "C" void kernel_launch(void* const* d_in, const int* in_sizes, int n_in,
                              void* d_out, int out_size)
{
    (void)in_sizes; (void)n_in; (void)out_size;
    const float* x        = (const float*)d_in[0];
    const float* bases0   = (const float*)d_in[1];
    const float* w_lower  = (const float*)d_in[2];
    const float* b_lower  = (const float*)d_in[3];
    const float* w_cheese = (const float*)d_in[4];
    const float* b_cheese = (const float*)d_in[5];
    const float* w_upper  = (const float*)d_in[6];
    const float* c_sc     = (const float*)d_in[7];
    const float* c_ham    = (const float*)d_in[8];
    float* out = (float*)d_out;

    dim3 gg(32, 4, 8);

    k_l2norm<<<512, 128>>>(bases0);
    k_gemm512<0><<<gg, 256>>>(w_lower, x, b_lower, nullptr, nullptr, nullptr, nullptr);

    // coef init: softmax(x^T bases)
    k_xtb<<<dim3(32, 8), 256>>>();
    k_softmax<<<4096, 256>>>();

    for (int it = 0; it < 6; ++it) {
        k_xtb<<<dim3(32, 8), 256>>>();
        k_btb<<<dim3(8, 16), 256>>>();
        k_coef_update<<<dim3(128, 8), 256>>>();
        k_xc_part<<<dim3(4, 8, 8), 256>>>();
        k_ctc_part<<<dim3(8, 16), 256>>>();
        k_bases_update<<<dim3(8, 8), 256>>>();
    }

    // final differentiable coef refinement
    k_xtb<<<dim3(32, 8), 256>>>();
    k_btb<<<dim3(8, 16), 256>>>();
    k_coef_update<<<dim3(128, 8), 256>>>();

    // reconstruct, cheese, upper + residual + relu
    k_ham<<<dim3(64, 8, 8), 256>>>();
    k_gemm512<1><<<gg, 256>>>(w_cheese, nullptr, b_cheese, nullptr, nullptr, nullptr, nullptr);
    k_gemm512<2><<<gg, 256>>>(w_upper, nullptr, nullptr, x, c_ham, c_sc, out);
}

// round 5
// speedup vs baseline: 1.3737x; 1.3737x over previous
#include <cuda_runtime.h>
#include <cuda_bf16.h>
#include <cstdint>

#define EPSF 1e-6f
constexpr int B_ = 8;      // batch
constexpr int C_ = 512;    // channels (= D)
constexpr int N_ = 4096;   // spatial H*W
constexpr int R_ = 64;     // bases rank

// ---------------- scratch (device globals; no allocation) ----------------
__device__ float g_h1[(size_t)B_*C_*N_];              // relu(lower conv) fp32 [b][c][n]
__device__ __nv_bfloat16 g_x_hi  [(size_t)B_*C_*N_];  // x split      [b][c][n]
__device__ __nv_bfloat16 g_x_lo  [(size_t)B_*C_*N_];
__device__ __nv_bfloat16 g_ham_hi[(size_t)B_*C_*N_];  // ham split    [b][c][n]
__device__ __nv_bfloat16 g_ham_lo[(size_t)B_*C_*N_];
__device__ __nv_bfloat16 g_h2_hi [(size_t)B_*C_*N_];  // cheese split [b][c][n]
__device__ __nv_bfloat16 g_h2_lo [(size_t)B_*C_*N_];
__device__ __nv_bfloat16 g_wl_hi[(size_t)C_*C_], g_wl_lo[(size_t)C_*C_];
__device__ __nv_bfloat16 g_wc_hi[(size_t)C_*C_], g_wc_lo[(size_t)C_*C_];
__device__ __nv_bfloat16 g_wu_hi[(size_t)C_*C_], g_wu_lo[(size_t)C_*C_];
__device__ float g_bases[(size_t)B_*C_*R_];
__device__ float g_coef [(size_t)B_*N_*R_];
__device__ float g_xtb  [(size_t)B_*N_*R_];
__device__ float g_btb  [(size_t)B_*R_*R_];
__device__ float g_ctc_part[(size_t)16*B_*R_*R_];
__device__ float g_xc_part [(size_t)8*B_*C_*R_];

// ---------------- PTX helpers (sm_80+ features only) ----------------
__device__ __forceinline__ uint32_t smem_u32(const void* p) {
    uint32_t a;
    asm("{ .reg .u64 t; cvta.to.shared.u64 t, %1; cvt.u32.u64 %0, t; }" : "=r"(a) : "l"(p));
    return a;
}
__device__ __forceinline__ void cpa16(uint32_t dst, const void* src) {
    asm volatile("cp.async.ca.shared.global [%0], [%1], 16;" :: "r"(dst), "l"(src));
}
#define CP_COMMIT() asm volatile("cp.async.commit_group;" ::: "memory")
#define CP_WAIT0()  asm volatile("cp.async.wait_group 0;" ::: "memory")

__device__ __forceinline__ void mma16816(float* c, const unsigned* a, const unsigned* b) {
    asm volatile("mma.sync.aligned.m16n8k16.row.col.f32.bf16.bf16.f32 "
        "{%0,%1,%2,%3}, {%4,%5,%6,%7}, {%8,%9}, {%0,%1,%2,%3};"
        : "+f"(c[0]), "+f"(c[1]), "+f"(c[2]), "+f"(c[3])
        : "r"(a[0]), "r"(a[1]), "r"(a[2]), "r"(a[3]), "r"(b[0]), "r"(b[1]));
}
__device__ __forceinline__ void ldsm4(unsigned* r, uint32_t addr) {
    asm volatile("ldmatrix.sync.aligned.m8n8.x4.shared.b16 {%0,%1,%2,%3}, [%4];"
        : "=r"(r[0]), "=r"(r[1]), "=r"(r[2]), "=r"(r[3]) : "r"(addr));
}
__device__ __forceinline__ void ldsm4t(unsigned* r, uint32_t addr) {
    asm volatile("ldmatrix.sync.aligned.m8n8.x4.trans.shared.b16 {%0,%1,%2,%3}, [%4];"
        : "=r"(r[0]), "=r"(r[1]), "=r"(r[2]), "=r"(r[3]) : "r"(addr));
}

// ---------------- split prep ----------------
// SELW: 0 -> wl, 1 -> wc, 2 -> wu
template<int SELW>
__global__ void k_splitw(const float* __restrict__ w)
{
    __nv_bfloat16* hi = (SELW == 0) ? g_wl_hi : (SELW == 1) ? g_wc_hi : g_wu_hi;
    __nv_bfloat16* lo = (SELW == 0) ? g_wl_lo : (SELW == 1) ? g_wc_lo : g_wu_lo;
    int i = blockIdx.x * 256 + threadIdx.x;
    float v = w[i];
    __nv_bfloat16 h = __float2bfloat16(v);
    hi[i] = h;
    lo[i] = __float2bfloat16(v - __bfloat162float(h));
}

__global__ void k_splitx(const float* __restrict__ x)
{
    size_t i = ((size_t)blockIdx.x * 256 + threadIdx.x) * 4;
    float4 v = *(const float4*)(x + i);
    __nv_bfloat16 h0 = __float2bfloat16(v.x), h1 = __float2bfloat16(v.y);
    __nv_bfloat16 h2 = __float2bfloat16(v.z), h3 = __float2bfloat16(v.w);
    *(__nv_bfloat162*)(g_x_hi + i)     = {h0, h1};
    *(__nv_bfloat162*)(g_x_hi + i + 2) = {h2, h3};
    __nv_bfloat16 l0 = __float2bfloat16(v.x - __bfloat162float(h0));
    __nv_bfloat16 l1 = __float2bfloat16(v.y - __bfloat162float(h1));
    __nv_bfloat16 l2 = __float2bfloat16(v.z - __bfloat162float(h2));
    __nv_bfloat16 l3 = __float2bfloat16(v.w - __bfloat162float(h3));
    *(__nv_bfloat162*)(g_x_lo + i)     = {l0, l1};
    *(__nv_bfloat162*)(g_x_lo + i + 2) = {l2, l3};
}

// ================= mma.sync split-bf16 GEMM =================
// D[b][m][n] = sum_k A[m][k] * Bg[b][k][n]; A 512x512 row-major split bf16,
// Bg natural [k][n] split bf16. BM=BN=128, BK=32, 256 thr, warp tile 64x32.
// SEL 0: A=wl, B=x    -> relu(D+bias) -> g_h1 fp32
// SEL 1: A=wc, B=ham  -> relu(D+bias) -> g_h2 split bf16
// SEL 2: A=wu, B=h2   -> relu(ch*D + cs*shortcut) -> dout fp32
constexpr int AST   = 56;          // A smem row stride (elems), 112B
constexpr int BST   = 136;         // B smem row stride (elems), 272B
constexpr int ATILE = 128 * AST;   // elems per A operand tile
constexpr int BTILE = 32 * BST;    // elems per B operand tile
constexpr int STAGE_E = 2*ATILE + 2*BTILE;
constexpr int MG_SMEM = 2 * STAGE_E * 2;         // 92160 bytes

template<int SEL>
__global__ __launch_bounds__(256, 1) void k_mgemm(
    const float* __restrict__ bias, const float* __restrict__ shortcut,
    const float* __restrict__ p_ham, const float* __restrict__ p_sc,
    float* __restrict__ dout)
{
    const __nv_bfloat16* A_hi = (SEL == 0) ? g_wl_hi : (SEL == 1) ? g_wc_hi : g_wu_hi;
    const __nv_bfloat16* A_lo = (SEL == 0) ? g_wl_lo : (SEL == 1) ? g_wc_lo : g_wu_lo;
    const __nv_bfloat16* Bg_hi = (SEL == 0) ? g_x_hi : (SEL == 1) ? g_ham_hi : g_h2_hi;
    const __nv_bfloat16* Bg_lo = (SEL == 0) ? g_x_lo : (SEL == 1) ? g_ham_lo : g_h2_lo;

    extern __shared__ __nv_bfloat16 sm[];
    const int tid = threadIdx.x, lane = tid & 31, wid = tid >> 5;
    const int b = blockIdx.z, m0 = blockIdx.y * 128, n0 = blockIdx.x * 128;
    const int wm = (wid & 1) * 64, wn = (wid >> 1) * 32;
    uint32_t sb = smem_u32(sm);

    const __nv_bfloat16* Ah = A_hi + (size_t)m0 * C_;
    const __nv_bfloat16* Al = A_lo + (size_t)m0 * C_;
    const __nv_bfloat16* Bh = Bg_hi + (size_t)b*C_*N_ + n0;
    const __nv_bfloat16* Bl = Bg_lo + (size_t)b*C_*N_ + n0;

    const int a_row = tid >> 2, a_c8 = (tid & 3) * 8;    // A: 2 chunks, rows +64
    const int b_row = tid >> 4, b_c8 = (tid & 15) * 8;   // B: 2 chunks, rows +16

    float acc[4][4][4];
#pragma unroll
    for (int mt = 0; mt < 4; mt++)
#pragma unroll
        for (int nt = 0; nt < 4; nt++)
#pragma unroll
            for (int j = 0; j < 4; j++) acc[mt][nt][j] = 0.f;

    auto issue_stage = [&](int k0, int s) {
        uint32_t so = sb + s * (STAGE_E * 2);
#pragma unroll
        for (int it = 0; it < 2; it++) {
            int row = a_row + it * 64;
            uint32_t d = so + (row * AST + a_c8) * 2;
            cpa16(d,             Ah + (size_t)row * C_ + k0 + a_c8);
            cpa16(d + ATILE * 2, Al + (size_t)row * C_ + k0 + a_c8);
        }
#pragma unroll
        for (int it = 0; it < 2; it++) {
            int row = b_row + it * 16;
            uint32_t d = so + (2*ATILE + row * BST + b_c8) * 2;
            cpa16(d,             Bh + (size_t)(k0 + row) * N_ + b_c8);
            cpa16(d + BTILE * 2, Bl + (size_t)(k0 + row) * N_ + b_c8);
        }
        CP_COMMIT();
    };

    const int g8 = lane >> 3;
    const int lm_r = (lane & 7) + (g8 & 1) * 8;
    const int lm_c = (g8 >> 1) * 8;

    auto compute_stage = [&](int s) {
        uint32_t so = sb + s * (STAGE_E * 2);
#pragma unroll
        for (int ks = 0; ks < 2; ks++) {
            unsigned ah[4][4], alr[4][4], bh[4][2], blr[4][2];
#pragma unroll
            for (int mt = 0; mt < 4; mt++) {
                uint32_t ad = so + ((wm + mt*16 + lm_r) * AST + ks*16 + lm_c) * 2;
                ldsm4(ah[mt], ad);
                ldsm4(alr[mt], ad + ATILE * 2);
            }
#pragma unroll
            for (int ng = 0; ng < 2; ng++) {
                unsigned t4[4];
                uint32_t bd = so + (2*ATILE + (ks*16 + lm_r) * BST + wn + ng*16 + lm_c) * 2;
                ldsm4t(t4, bd);
                bh[ng*2][0] = t4[0]; bh[ng*2][1] = t4[1];
                bh[ng*2+1][0] = t4[2]; bh[ng*2+1][1] = t4[3];
                ldsm4t(t4, bd + BTILE * 2);
                blr[ng*2][0] = t4[0]; blr[ng*2][1] = t4[1];
                blr[ng*2+1][0] = t4[2]; blr[ng*2+1][1] = t4[3];
            }
#pragma unroll
            for (int mt = 0; mt < 4; mt++)
#pragma unroll
                for (int nt = 0; nt < 4; nt++) {
                    mma16816(acc[mt][nt], ah[mt],  bh[nt]);
                    mma16816(acc[mt][nt], ah[mt],  blr[nt]);
                    mma16816(acc[mt][nt], alr[mt], bh[nt]);
                }
        }
    };

    issue_stage(0, 0);
    CP_WAIT0();
    __syncthreads();
#pragma unroll 1
    for (int i = 0; i < 16; i++) {
        int s = i & 1;
        if (i < 15) issue_stage((i + 1) * 32, s ^ 1);
        compute_stage(s);
        if (i < 15) { CP_WAIT0(); __syncthreads(); }
    }

    // epilogue
    float ch = 1.f, csc = 1.f;
    if (SEL == 2) { ch = p_ham[0]; csc = p_sc[0]; }
#pragma unroll
    for (int mt = 0; mt < 4; mt++) {
        int r0 = m0 + wm + mt*16 + (lane >> 2);
        float bv0 = 0.f, bv1 = 0.f;
        if (SEL != 2) { bv0 = bias[r0]; bv1 = bias[r0 + 8]; }
#pragma unroll
        for (int nt = 0; nt < 4; nt++) {
            int c = n0 + wn + nt*8 + (lane & 3) * 2;
            float v0 = acc[mt][nt][0], v1 = acc[mt][nt][1];
            float v2 = acc[mt][nt][2], v3 = acc[mt][nt][3];
            size_t o0 = (size_t)b*C_*N_ + (size_t)r0 * N_ + c;
            size_t o1 = o0 + (size_t)8 * N_;
            if (SEL == 0) {
                float2 s0 = {fmaxf(v0 + bv0, 0.f), fmaxf(v1 + bv0, 0.f)};
                float2 s1 = {fmaxf(v2 + bv1, 0.f), fmaxf(v3 + bv1, 0.f)};
                *(float2*)(g_h1 + o0) = s0;
                *(float2*)(g_h1 + o1) = s1;
            } else if (SEL == 1) {
                v0 = fmaxf(v0 + bv0, 0.f); v1 = fmaxf(v1 + bv0, 0.f);
                v2 = fmaxf(v2 + bv1, 0.f); v3 = fmaxf(v3 + bv1, 0.f);
                __nv_bfloat16 h0 = __float2bfloat16(v0), h1 = __float2bfloat16(v1);
                __nv_bfloat16 h2 = __float2bfloat16(v2), h3 = __float2bfloat16(v3);
                *(__nv_bfloat162*)(g_h2_hi + o0) = {h0, h1};
                *(__nv_bfloat162*)(g_h2_hi + o1) = {h2, h3};
                *(__nv_bfloat162*)(g_h2_lo + o0) =
                    {__float2bfloat16(v0 - __bfloat162float(h0)),
                     __float2bfloat16(v1 - __bfloat162float(h1))};
                *(__nv_bfloat162*)(g_h2_lo + o1) =
                    {__float2bfloat16(v2 - __bfloat162float(h2)),
                     __float2bfloat16(v3 - __bfloat162float(h3))};
            } else {
                float2 s0 = *(const float2*)(shortcut + o0);
                float2 s1 = *(const float2*)(shortcut + o1);
                float2 w0 = {fmaxf(ch*v0 + csc*s0.x, 0.f), fmaxf(ch*v1 + csc*s0.y, 0.f)};
                float2 w1 = {fmaxf(ch*v2 + csc*s1.x, 0.f), fmaxf(ch*v3 + csc*s1.y, 0.f)};
                *(float2*)(dout + o0) = w0;
                *(float2*)(dout + o1) = w1;
            }
        }
    }
}

// ================= NMF kernels (proven R1 versions) =================
__global__ void k_l2norm(const float* __restrict__ b0)
{
    int b = blockIdx.x >> 6, r = blockIdx.x & 63;
    const float* src = b0 + (size_t)b*C_*R_ + r;
    float ss = 0.f;
    for (int d = threadIdx.x; d < C_; d += 128) { float v = src[(size_t)d*R_]; ss += v*v; }
    __shared__ float red[128];
    red[threadIdx.x] = ss; __syncthreads();
    for (int s = 64; s > 0; s >>= 1) {
        if (threadIdx.x < s) red[threadIdx.x] += red[threadIdx.x + s];
        __syncthreads();
    }
    float inv = 1.f / fmaxf(sqrtf(red[0]), 1e-12f);
    float* dst = g_bases + (size_t)b*C_*R_ + r;
    for (int d = threadIdx.x; d < C_; d += 128) dst[(size_t)d*R_] = src[(size_t)d*R_] * inv;
}

__global__ __launch_bounds__(256) void k_xtb()
{
    int n0 = blockIdx.x * 128, b = blockIdx.y;
    const float* xb = g_h1    + (size_t)b*C_*N_;
    const float* bp = g_bases + (size_t)b*C_*R_;
    __shared__ float xs[16][128];
    __shared__ float bs[16][64];
    int t = threadIdx.x;
    int tn = t & 15, tr = t >> 4;
    int lrow = t >> 4, xcol = (t & 15) * 8, bcol = (t & 15) * 4;
    float acc[8][4];
#pragma unroll
    for (int i = 0; i < 8; i++)
#pragma unroll
        for (int j = 0; j < 4; j++) acc[i][j] = 0.f;

    for (int d0 = 0; d0 < C_; d0 += 16) {
        float4 x0 = *(const float4*)(xb + (size_t)(d0+lrow)*N_ + n0 + xcol);
        float4 x1 = *(const float4*)(xb + (size_t)(d0+lrow)*N_ + n0 + xcol + 4);
        float4 b0 = *(const float4*)(bp + (size_t)(d0+lrow)*R_ + bcol);
        __syncthreads();
        *(float4*)&xs[lrow][xcol]   = x0;
        *(float4*)&xs[lrow][xcol+4] = x1;
        *(float4*)&bs[lrow][bcol]   = b0;
        __syncthreads();
#pragma unroll
        for (int k = 0; k < 16; k++) {
            float4 a0 = *(float4*)&xs[k][tn*8], a1 = *(float4*)&xs[k][tn*8+4];
            float4 bv = *(float4*)&bs[k][tr*4];
            float av[8] = {a0.x,a0.y,a0.z,a0.w,a1.x,a1.y,a1.z,a1.w};
            float br[4] = {bv.x,bv.y,bv.z,bv.w};
#pragma unroll
            for (int i = 0; i < 8; i++)
#pragma unroll
                for (int j = 0; j < 4; j++) acc[i][j] += av[i]*br[j];
        }
    }
    float* op = g_xtb + ((size_t)b*N_ + n0 + tn*8)*R_ + tr*4;
#pragma unroll
    for (int i = 0; i < 8; i++) {
        float4 o = {acc[i][0], acc[i][1], acc[i][2], acc[i][3]};
        *(float4*)(op + (size_t)i*R_) = o;
    }
}

__global__ void k_softmax()
{
    int row  = blockIdx.x * 8 + (threadIdx.x >> 5);
    int lane = threadIdx.x & 31;
    const float* xp = g_xtb + (size_t)row*R_;
    float v0 = xp[lane], v1 = xp[lane+32];
    float m = fmaxf(v0, v1);
#pragma unroll
    for (int o = 16; o; o >>= 1) m = fmaxf(m, __shfl_xor_sync(0xffffffffu, m, o));
    float e0 = __expf(v0 - m), e1 = __expf(v1 - m);
    float s = e0 + e1;
#pragma unroll
    for (int o = 16; o; o >>= 1) s += __shfl_xor_sync(0xffffffffu, s, o);
    float inv = 1.f / s;
    float* op = g_coef + (size_t)row*R_;
    op[lane] = e0*inv; op[lane+32] = e1*inv;
}

__global__ __launch_bounds__(256) void k_btb()
{
    int b = blockIdx.x, g = blockIdx.y;
    const float* bp = g_bases + (size_t)b*C_*R_;
    __shared__ float sh[32][64];
    int t = threadIdx.x;
    int r = g*4 + (t >> 6), s = t & 63;
    float acc = 0.f;
    for (int d0 = 0; d0 < C_; d0 += 32) {
        __syncthreads();
        for (int i = t; i < 2048; i += 256) sh[i>>6][i&63] = bp[(size_t)d0*R_ + i];
        __syncthreads();
#pragma unroll
        for (int d = 0; d < 32; d++) acc += sh[d][r]*sh[d][s];
    }
    g_btb[((size_t)b*R_ + r)*R_ + s] = acc;
}

__global__ __launch_bounds__(256) void k_coef_update()
{
    int b = blockIdx.y, n0 = blockIdx.x * 32;
    __shared__ float bt[64][64];
    __shared__ float cr[32][64];
    int t = threadIdx.x;
    const float* bp = g_btb + (size_t)b*R_*R_;
    for (int i = t; i < 4096; i += 256) bt[i>>6][i&63] = bp[i];
    const float* cp = g_coef + ((size_t)b*N_ + n0)*R_;
    for (int i = t; i < 2048; i += 256) cr[i>>6][i&63] = cp[i];
    __syncthreads();
    int nl = t >> 3, r0 = (t & 7) * 8;
    float acc[8] = {0,0,0,0,0,0,0,0};
#pragma unroll 8
    for (int s = 0; s < 64; s++) {
        float c = cr[nl][s];
        float4 b0 = *(float4*)&bt[s][r0], b1 = *(float4*)&bt[s][r0+4];
        acc[0] += c*b0.x; acc[1] += c*b0.y; acc[2] += c*b0.z; acc[3] += c*b0.w;
        acc[4] += c*b1.x; acc[5] += c*b1.y; acc[6] += c*b1.z; acc[7] += c*b1.w;
    }
    const float* xp = g_xtb + ((size_t)b*N_ + n0 + nl)*R_ + r0;
    float* op = g_coef + ((size_t)b*N_ + n0 + nl)*R_ + r0;
#pragma unroll
    for (int j = 0; j < 8; j++) op[j] = cr[nl][r0+j] * xp[j] / (acc[j] + EPSF);
}

__global__ __launch_bounds__(256) void k_xc_part()
{
    int m0 = blockIdx.x * 128, b = blockIdx.y, sp = blockIdx.z;
    const float* xb = g_h1   + (size_t)b*C_*N_ + sp*512;
    const float* cp = g_coef + ((size_t)b*N_ + sp*512)*R_;
    __shared__ float xs[16][128];
    __shared__ float cs[16][64];
    int t = threadIdx.x;
    int td = t & 15, tr = t >> 4;
    int lrow = t >> 1, lnc = (t & 1) * 8;
    int crow = t >> 4, ccol = (t & 15) * 4;
    float acc[8][4];
#pragma unroll
    for (int i = 0; i < 8; i++)
#pragma unroll
        for (int j = 0; j < 4; j++) acc[i][j] = 0.f;

    for (int n0 = 0; n0 < 512; n0 += 16) {
        float4 x0 = *(const float4*)(xb + (size_t)(m0+lrow)*N_ + n0 + lnc);
        float4 x1 = *(const float4*)(xb + (size_t)(m0+lrow)*N_ + n0 + lnc + 4);
        float4 c0 = *(const float4*)(cp + (size_t)(n0+crow)*R_ + ccol);
        __syncthreads();
        xs[lnc+0][lrow] = x0.x; xs[lnc+1][lrow] = x0.y;
        xs[lnc+2][lrow] = x0.z; xs[lnc+3][lrow] = x0.w;
        xs[lnc+4][lrow] = x1.x; xs[lnc+5][lrow] = x1.y;
        xs[lnc+6][lrow] = x1.z; xs[lnc+7][lrow] = x1.w;
        *(float4*)&cs[crow][ccol] = c0;
        __syncthreads();
#pragma unroll
        for (int k = 0; k < 16; k++) {
            float4 a0 = *(float4*)&xs[k][td*8], a1 = *(float4*)&xs[k][td*8+4];
            float4 cv = *(float4*)&cs[k][tr*4];
            float av[8] = {a0.x,a0.y,a0.z,a0.w,a1.x,a1.y,a1.z,a1.w};
            float cvv[4] = {cv.x,cv.y,cv.z,cv.w};
#pragma unroll
            for (int i = 0; i < 8; i++)
#pragma unroll
                for (int j = 0; j < 4; j++) acc[i][j] += av[i]*cvv[j];
        }
    }
#pragma unroll
    for (int i = 0; i < 8; i++) {
        float* op = g_xc_part + ((size_t)(sp*8 + b)*C_ + m0 + td*8 + i)*R_ + tr*4;
        float4 o = {acc[i][0], acc[i][1], acc[i][2], acc[i][3]};
        *(float4*)op = o;
    }
}

__global__ __launch_bounds__(256) void k_ctc_part()
{
    int b = blockIdx.x, sp = blockIdx.y;
    const float* cp = g_coef + ((size_t)b*N_ + sp*256)*R_;
    __shared__ float sh[32][64];
    int t = threadIdx.x;
    int rg = t >> 4, cg = t & 15;
    float acc[4][4];
#pragma unroll
    for (int i = 0; i < 4; i++)
#pragma unroll
        for (int j = 0; j < 4; j++) acc[i][j] = 0.f;

    for (int n0 = 0; n0 < 256; n0 += 32) {
        __syncthreads();
        for (int i = t; i < 2048; i += 256) sh[i>>6][i&63] = cp[(size_t)n0*R_ + i];
        __syncthreads();
#pragma unroll 4
        for (int n = 0; n < 32; n++) {
            float4 a = *(float4*)&sh[n][rg*4];
            float4 c = *(float4*)&sh[n][cg*4];
            float av[4] = {a.x,a.y,a.z,a.w}, cv[4] = {c.x,c.y,c.z,c.w};
#pragma unroll
            for (int i = 0; i < 4; i++)
#pragma unroll
                for (int j = 0; j < 4; j++) acc[i][j] += av[i]*cv[j];
        }
    }
    float* op = g_ctc_part + ((size_t)(sp*8 + b)*R_ + rg*4)*R_ + cg*4;
#pragma unroll
    for (int i = 0; i < 4; i++) {
        float4 o = {acc[i][0], acc[i][1], acc[i][2], acc[i][3]};
        *(float4*)(op + (size_t)i*R_) = o;
    }
}

__global__ __launch_bounds__(256) void k_bases_update()
{
    int b = blockIdx.x, d0 = blockIdx.y * 64;
    __shared__ float ct[64][64];
    __shared__ float br[64][64];
    int t = threadIdx.x;
    for (int i = t; i < 4096; i += 256) {
        float s = 0.f;
#pragma unroll
        for (int p = 0; p < 16; p++) s += g_ctc_part[(size_t)(p*8 + b)*4096 + i];
        ct[i>>6][i&63] = s;
    }
    const float* bp = g_bases + ((size_t)b*C_ + d0)*R_;
    for (int i = t; i < 4096; i += 256) br[i>>6][i&63] = bp[i];
    __syncthreads();
    int dl = t >> 2, r0 = (t & 3) * 16;
    float acc[16];
#pragma unroll
    for (int j = 0; j < 16; j++) acc[j] = 0.f;
#pragma unroll 4
    for (int s = 0; s < 64; s++) {
        float bv = br[dl][s];
#pragma unroll
        for (int j4 = 0; j4 < 16; j4 += 4) {
            float4 v = *(float4*)&ct[s][r0 + j4];
            acc[j4+0] += bv*v.x; acc[j4+1] += bv*v.y;
            acc[j4+2] += bv*v.z; acc[j4+3] += bv*v.w;
        }
    }
    float xcs[16];
#pragma unroll
    for (int j = 0; j < 16; j++) xcs[j] = 0.f;
#pragma unroll
    for (int p = 0; p < 8; p++) {
        const float* xp = g_xc_part + ((size_t)(p*8 + b)*C_ + d0 + dl)*R_ + r0;
#pragma unroll
        for (int j4 = 0; j4 < 16; j4 += 4) {
            float4 v = *(const float4*)(xp + j4);
            xcs[j4+0] += v.x; xcs[j4+1] += v.y; xcs[j4+2] += v.z; xcs[j4+3] += v.w;
        }
    }
    float* op = g_bases + ((size_t)b*C_ + d0 + dl)*R_ + r0;
#pragma unroll
    for (int j = 0; j < 16; j++) op[j] = br[dl][r0+j] * xcs[j] / (acc[j] + EPSF);
}

// ---------------- ham[b,d,n] = sum_r bases*coef -> split bf16 [b][d][n] ----------------
__global__ __launch_bounds__(256) void k_ham()
{
    int b = blockIdx.z, d0 = blockIdx.y * 64, n0 = blockIdx.x * 64;
    __shared__ float bs[64][65];
    __shared__ float cs[64][65];
    int t = threadIdx.x;
    const float* bp = g_bases + ((size_t)b*C_ + d0)*R_;
    const float* cp = g_coef  + ((size_t)b*N_ + n0)*R_;
    for (int i = t; i < 4096; i += 256) {
        bs[i>>6][i&63] = bp[i];
        cs[i>>6][i&63] = cp[i];
    }
    __syncthreads();
    int td = t >> 4, tn = t & 15;
    float acc[4][4];
#pragma unroll
    for (int i = 0; i < 4; i++)
#pragma unroll
        for (int j = 0; j < 4; j++) acc[i][j] = 0.f;
#pragma unroll 8
    for (int r = 0; r < 64; r++) {
        float bv[4], cv[4];
#pragma unroll
        for (int i = 0; i < 4; i++) bv[i] = bs[td*4+i][r];
#pragma unroll
        for (int j = 0; j < 4; j++) cv[j] = cs[tn*4+j][r];
#pragma unroll
        for (int i = 0; i < 4; i++)
#pragma unroll
            for (int j = 0; j < 4; j++) acc[i][j] += bv[i]*cv[j];
    }
#pragma unroll
    for (int i = 0; i < 4; i++) {
        size_t o = (size_t)b*C_*N_ + (size_t)(d0 + td*4 + i)*N_ + n0 + tn*4;
        __nv_bfloat16 h[4], l[4];
#pragma unroll
        for (int j = 0; j < 4; j++) {
            float v = acc[i][j];
            h[j] = __float2bfloat16(v);
            l[j] = __float2bfloat16(v - __bfloat162float(h[j]));
        }
        *(__nv_bfloat162*)(g_ham_hi + o)     = {h[0], h[1]};
        *(__nv_bfloat162*)(g_ham_hi + o + 2) = {h[2], h[3]};
        *(__nv_bfloat162*)(g_ham_lo + o)     = {l[0], l[1]};
        *(__nv_bfloat162*)(g_ham_lo + o + 2) = {l[2], l[3]};
    }
}

// ---------------- host driver ----------------
extern "C" void kernel_launch(void* const* d_in, const int* in_sizes, int n_in,
                              void* d_out, int out_size)
{
    (void)in_sizes; (void)n_in; (void)out_size;
    const float* x        = (const float*)d_in[0];
    const float* bases0   = (const float*)d_in[1];
    const float* w_lower  = (const float*)d_in[2];
    const float* b_lower  = (const float*)d_in[3];
    const float* w_cheese = (const float*)d_in[4];
    const float* b_cheese = (const float*)d_in[5];
    const float* w_upper  = (const float*)d_in[6];
    const float* c_sc     = (const float*)d_in[7];
    const float* c_ham    = (const float*)d_in[8];
    float* out = (float*)d_out;

    static bool attr_done = false;
    if (!attr_done) {
        cudaFuncSetAttribute(k_mgemm<0>, cudaFuncAttributeMaxDynamicSharedMemorySize, MG_SMEM);
        cudaFuncSetAttribute(k_mgemm<1>, cudaFuncAttributeMaxDynamicSharedMemorySize, MG_SMEM);
        cudaFuncSetAttribute(k_mgemm<2>, cudaFuncAttributeMaxDynamicSharedMemorySize, MG_SMEM);
        attr_done = true;
    }

    dim3 gg(32, 4, 8);

    k_l2norm<<<512, 128>>>(bases0);
    k_splitw<0><<<1024, 256>>>(w_lower);
    k_splitw<1><<<1024, 256>>>(w_cheese);
    k_splitw<2><<<1024, 256>>>(w_upper);
    k_splitx<<<16384, 256>>>(x);

    // lower bread: h1 = relu(W_lower @ x + b)
    k_mgemm<0><<<gg, 256, MG_SMEM>>>(b_lower, nullptr, nullptr, nullptr, nullptr);

    // coef init: softmax(h1^T bases)
    k_xtb<<<dim3(32, 8), 256>>>();
    k_softmax<<<4096, 256>>>();

    for (int it = 0; it < 6; ++it) {
        k_xtb<<<dim3(32, 8), 256>>>();
        k_btb<<<dim3(8, 16), 256>>>();
        k_coef_update<<<dim3(128, 8), 256>>>();
        k_xc_part<<<dim3(4, 8, 8), 256>>>();
        k_ctc_part<<<dim3(8, 16), 256>>>();
        k_bases_update<<<dim3(8, 8), 256>>>();
    }

    // final differentiable coef refinement
    k_xtb<<<dim3(32, 8), 256>>>();
    k_btb<<<dim3(8, 16), 256>>>();
    k_coef_update<<<dim3(128, 8), 256>>>();

    // reconstruct (split bf16), cheese, upper + residual + relu
    k_ham<<<dim3(64, 8, 8), 256>>>();
    k_mgemm<1><<<gg, 256, MG_SMEM>>>(b_cheese, nullptr, nullptr, nullptr, nullptr);
    k_mgemm<2><<<gg, 256, MG_SMEM>>>(nullptr, x, c_ham, c_sc, out);
}